// round 5
// baseline (speedup 1.0000x reference)
#include <cuda_runtime.h>
#include <cuda_fp16.h>
#include <cstdint>

// ---------------------------------------------------------------------------
// Problem constants
// ---------------------------------------------------------------------------
static constexpr int NROWS = 65536;
static constexpr int APPD  = 1024;
static constexpr int SPDIM = 512;

static constexpr int BM = 128, BN = 128, BK = 64;  // k-elements per stage

// Both modes: A fp16 (128x64x2=16KB) + B fp16 (128x64x2=16KB) per stage, x2
static constexpr int SMEMB = 2 * (BM * BK * 2 + BN * BK * 2);  // 65536

// ---------------------------------------------------------------------------
// Device scratch (allocation-free rule: __device__ globals)
// ---------------------------------------------------------------------------
__device__ __half g_B1h[512 * 1536];          // GEMM1 B: [n][k] = Wcat[k][n], fp16
__device__ __half g_B2h[512 * 512];           // GEMM2 B: [h][j] = W3flat[j][h], fp16
__device__ float  g_bias1[512];               // b1 + b2 (flattened c*32+s)
__device__ float  g_bias2[512];               // sum_c b3[c][:]
__device__ __half g_Hh[(size_t)65536 * 512];  // intermediate h, fp16

// ---------------------------------------------------------------------------
// Helpers (plain sm_80+ PTX only)
// ---------------------------------------------------------------------------
__device__ __forceinline__ void cp16(uint32_t smem_dst, const void* gsrc) {
    asm volatile("cp.async.cg.shared.global [%0], [%1], 16;" :: "r"(smem_dst), "l"(gsrc));
}
__device__ __forceinline__ void cp_commit() { asm volatile("cp.async.commit_group;"); }
template <int N>
__device__ __forceinline__ void cp_wait() { asm volatile("cp.async.wait_group %0;" :: "n"(N)); }

__device__ __forceinline__ uint32_t pack_h2(float lo, float hi) {
    __half2 h = __floats2half2_rn(lo, hi);
    return *reinterpret_cast<uint32_t*>(&h);
}

// m16n8k16 fp16 mma, fp32 accum.
__device__ __forceinline__ void mma16(float* d, const uint32_t* a, uint32_t b0, uint32_t b1) {
    asm volatile(
        "mma.sync.aligned.m16n8k16.row.col.f32.f16.f16.f32 "
        "{%0,%1,%2,%3}, {%4,%5,%6,%7}, {%8,%9}, {%0,%1,%2,%3};"
        : "+f"(d[0]), "+f"(d[1]), "+f"(d[2]), "+f"(d[3])
        : "r"(a[0]), "r"(a[1]), "r"(a[2]), "r"(a[3]), "r"(b0), "r"(b1));
}

// ---------------------------------------------------------------------------
// Prep: transpose weights -> fp16, fuse biases
// ---------------------------------------------------------------------------
__global__ void prep_kernel(const float* __restrict__ W1, const float* __restrict__ b1,
                            const float* __restrict__ W2, const float* __restrict__ b2,
                            const float* __restrict__ W3, const float* __restrict__ b3) {
    int idx = blockIdx.x * 256 + threadIdx.x;
    if (idx < 512 * 1536) {  // B1h[n][k] = Wcat[k][n];  n = c*32+s
        int n = idx / 1536, k = idx % 1536;
        int c = n >> 5, s = n & 31;
        float v = (k < APPD) ? W1[((size_t)c * APPD + k) * 32 + s]
                             : W2[((size_t)c * SPDIM + (k - APPD)) * 32 + s];
        g_B1h[idx] = __float2half_rn(v);
        return;
    }
    int i2 = idx - 512 * 1536;
    if (i2 < 512 * 512) {  // B2h[h][j] = W3flat[j][h]
        int h = i2 / 512, j = i2 % 512;
        g_B2h[i2] = __float2half_rn(W3[(size_t)j * 512 + h]);
        return;
    }
    int i3 = i2 - 512 * 512;
    if (i3 < 512) { g_bias1[i3] = b1[i3] + b2[i3]; return; }
    int i4 = i3 - 512;
    if (i4 < 512) {
        float s = 0.f;
        #pragma unroll
        for (int c = 0; c < 16; c++) s += b3[c * 512 + i4];
        g_bias2[i4] = s;
    }
}

// ---------------------------------------------------------------------------
// A loader MODE1: LDG fp32 -> cvt fp16 -> STS.128 (swizzled 128B rows)
// 128 rows x 64 fp32 -> 1024 x 16B fp16 chunks; 8 chunks per thread.
// ---------------------------------------------------------------------------
__device__ __forceinline__ void load_A_cvt(int tid, int row0, int kt, char* smemA,
                                           const float* __restrict__ A0,
                                           const float* __restrict__ A1) {
    const float* abase; int lda;
    if (kt * BK < APPD) { abase = A0 + kt * BK; lda = APPD; }
    else                { abase = A1 + (kt * BK - APPD); lda = SPDIM; }
    #pragma unroll
    for (int i = 0; i < 8; i++) {
        int v = i * 128 + tid;
        int r = v >> 3, q = v & 7;            // row, 16B-halfchunk (8 halves)
        const float* src = abase + (size_t)(row0 + r) * lda + 8 * q;
        float4 f0 = *(const float4*)(src);
        float4 f1 = *(const float4*)(src + 4);
        uint32_t h[4] = { pack_h2(f0.x, f0.y), pack_h2(f0.z, f0.w),
                          pack_h2(f1.x, f1.y), pack_h2(f1.z, f1.w) };
        *(uint4*)(smemA + r * 128 + ((16 * q) ^ (16 * (r & 7)))) = *(const uint4*)h;
    }
}

// B (and MODE2-A) loader: cp.async fp16, swizzled 128B rows
__device__ __forceinline__ void load_h16_tile(int tid, int n0g, int kt, int ldk,
                                              uint32_t s_dst, const __half* __restrict__ B) {
    #pragma unroll
    for (int i = 0; i < 8; i++) {
        int v = i * 128 + tid;
        int r = v >> 3, q = v & 7;
        cp16(s_dst + (uint32_t)(r * 128 + ((16 * q) ^ (16 * (r & 7)))),
             B + (size_t)(n0g + r) * ldk + kt * BK + 8 * q);
    }
}

// ---------------------------------------------------------------------------
// GEMM: MODE 1: [app|sp](fp32->fp16) @ B1h -> bias+relu -> g_Hh (fp16)
//       MODE 2: g_Hh @ B2h -> bias+relu -> out (fp32)
// CTA 128x128x64, 4 warps (2x2), warp tile 64x64, fp16 HMMA fp32 accum.
// ---------------------------------------------------------------------------
template <int MODE>
__global__ void __launch_bounds__(128, 2)
gemm_h(const float* __restrict__ A0, const float* __restrict__ A1,
       float* __restrict__ outp) {
    extern __shared__ char smem[];
    constexpr int ABYTES = BM * BK * 2;
    constexpr int STAGE  = ABYTES + BN * BK * 2;
    constexpr int NT     = (MODE == 1) ? (1536 / BK) : (512 / BK);

    const int tid = threadIdx.x;
    const int ncol0 = blockIdx.x * BN;   // n fastest -> A-sharing CTAs co-resident
    const int row0  = blockIdx.y * BM;
    const int lane = tid & 31, wid = tid >> 5;
    const int m0 = (wid & 1) * 64;
    const int n0 = (wid >> 1) * 64;
    const int g = lane >> 2, c = lane & 3;
    const int fxor = 16 * (g & 7);

    const __half* __restrict__ Bg = (MODE == 1) ? g_B1h : g_B2h;
    const int ldb = (MODE == 1) ? 1536 : 512;

    float acc[4][8][4];
    #pragma unroll
    for (int mt = 0; mt < 4; mt++)
        #pragma unroll
        for (int nt = 0; nt < 8; nt++)
            #pragma unroll
            for (int q = 0; q < 4; q++) acc[mt][nt][q] = 0.f;

    // stage 0
    {
        uint32_t s0 = (uint32_t)__cvta_generic_to_shared(smem);
        if (MODE == 1) load_A_cvt(tid, row0, 0, smem, A0, A1);
        else           load_h16_tile(tid, row0, 0, 512, s0, g_Hh);
        load_h16_tile(tid, ncol0, 0, ldb, s0 + ABYTES, Bg);
        cp_commit();
    }

    for (int t = 0; t < NT; t++) {
        if (t + 1 < NT) {
            char* nb = smem + ((t + 1) & 1) * STAGE;
            uint32_t nbs = (uint32_t)__cvta_generic_to_shared(nb);
            if (MODE == 1) load_A_cvt(tid, row0, t + 1, nb, A0, A1);
            else           load_h16_tile(tid, row0, t + 1, 512, nbs, g_Hh);
            load_h16_tile(tid, ncol0, t + 1, ldb, nbs + ABYTES, Bg);
            cp_commit();
            cp_wait<1>();
        } else {
            cp_wait<0>();
        }
        __syncthreads();

        const char* As = smem + (t & 1) * STAGE;
        const char* Bs = As + ABYTES;

        #pragma unroll
        for (int j = 0; j < 4; j++) {  // 4 x k16
            uint32_t a[4][4];
            #pragma unroll
            for (int mt = 0; mt < 4; mt++) {
                const char* ar0 = As + (m0 + 16 * mt + g) * 128;
                const char* ar1 = ar0 + 8 * 128;
                a[mt][0] = *(const uint32_t*)(ar0 + ((4 * c + 32 * j) ^ fxor));
                a[mt][1] = *(const uint32_t*)(ar1 + ((4 * c + 32 * j) ^ fxor));
                a[mt][2] = *(const uint32_t*)(ar0 + ((4 * c + 32 * j + 16) ^ fxor));
                a[mt][3] = *(const uint32_t*)(ar1 + ((4 * c + 32 * j + 16) ^ fxor));
            }
            #pragma unroll
            for (int nt = 0; nt < 8; nt++) {
                const char* br = Bs + (n0 + 8 * nt + g) * 128;
                uint32_t b0 = *(const uint32_t*)(br + ((4 * c + 32 * j) ^ fxor));
                uint32_t b1 = *(const uint32_t*)(br + ((4 * c + 32 * j + 16) ^ fxor));
                #pragma unroll
                for (int mt = 0; mt < 4; mt++) mma16(acc[mt][nt], a[mt], b0, b1);
            }
        }
        __syncthreads();
    }

    // Epilogue: bias + relu
    if (MODE == 1) {  // -> g_Hh (fp16)
        #pragma unroll
        for (int nt = 0; nt < 8; nt++) {
            const int ccol = ncol0 + n0 + 8 * nt + 2 * c;
            const float2 bv = *(const float2*)(g_bias1 + ccol);
            #pragma unroll
            for (int mt = 0; mt < 4; mt++) {
                const int r_ = row0 + m0 + 16 * mt + g;
                float x0 = fmaxf(acc[mt][nt][0] + bv.x, 0.f);
                float x1 = fmaxf(acc[mt][nt][1] + bv.y, 0.f);
                float x2 = fmaxf(acc[mt][nt][2] + bv.x, 0.f);
                float x3 = fmaxf(acc[mt][nt][3] + bv.y, 0.f);
                *(__half2*)(g_Hh + (size_t)r_ * 512 + ccol)       = __floats2half2_rn(x0, x1);
                *(__half2*)(g_Hh + (size_t)(r_ + 8) * 512 + ccol) = __floats2half2_rn(x2, x3);
            }
        }
    } else {          // -> out (fp32)
        #pragma unroll
        for (int nt = 0; nt < 8; nt++) {
            const int ccol = ncol0 + n0 + 8 * nt + 2 * c;
            const float2 bv = *(const float2*)(g_bias2 + ccol);
            #pragma unroll
            for (int mt = 0; mt < 4; mt++) {
                const int r_ = row0 + m0 + 16 * mt + g;
                float x0 = fmaxf(acc[mt][nt][0] + bv.x, 0.f);
                float x1 = fmaxf(acc[mt][nt][1] + bv.y, 0.f);
                float x2 = fmaxf(acc[mt][nt][2] + bv.x, 0.f);
                float x3 = fmaxf(acc[mt][nt][3] + bv.y, 0.f);
                *(float2*)(outp + (size_t)r_ * 512 + ccol)       = make_float2(x0, x1);
                *(float2*)(outp + (size_t)(r_ + 8) * 512 + ccol) = make_float2(x2, x3);
            }
        }
    }
}

// ---------------------------------------------------------------------------
// Launch
// ---------------------------------------------------------------------------
extern "C" void kernel_launch(void* const* d_in, const int* in_sizes, int n_in,
                              void* d_out, int out_size) {
    const float* app = (const float*)d_in[0];
    const float* sp  = (const float*)d_in[1];
    const float* W1  = (const float*)d_in[2];
    const float* b1  = (const float*)d_in[3];
    const float* W2  = (const float*)d_in[4];
    const float* b2  = (const float*)d_in[5];
    const float* W3  = (const float*)d_in[6];
    const float* b3  = (const float*)d_in[7];
    float* out = (float*)d_out;

    cudaFuncSetAttribute(gemm_h<1>, cudaFuncAttributeMaxDynamicSharedMemorySize, SMEMB);
    cudaFuncSetAttribute(gemm_h<2>, cudaFuncAttributeMaxDynamicSharedMemorySize, SMEMB);

    const int prep_elems = 512 * 1536 + 512 * 512 + 1024;
    prep_kernel<<<(prep_elems + 255) / 256, 256>>>(W1, b1, W2, b2, W3, b3);

    dim3 grid(512 / BN, NROWS / BM);  // (4, 512): n-blocks fastest -> A L2 reuse
    gemm_h<1><<<grid, 128, SMEMB>>>(app, sp, nullptr);
    gemm_h<2><<<grid, 128, SMEMB>>>(nullptr, nullptr, out);
}

// round 7
// speedup vs baseline: 1.0025x; 1.0025x over previous
#include <cuda_runtime.h>
#include <cuda_fp16.h>
#include <cstdint>

// ---------------------------------------------------------------------------
// Problem constants
// ---------------------------------------------------------------------------
static constexpr int NROWS = 65536;
static constexpr int APPD  = 1024;
static constexpr int SPDIM = 512;

static constexpr int BM = 128, BN = 128, BK = 64;  // k-elements per stage

// A fp16 (16KB) + B fp16 (16KB) per stage, x2 buffers
static constexpr int SMEMB = 2 * (BM * BK * 2 + BN * BK * 2);  // 65536

// ---------------------------------------------------------------------------
// Device scratch (allocation-free rule: __device__ globals)
// ---------------------------------------------------------------------------
__device__ __half g_B1h[512 * 1536];          // GEMM1 B: [n][k] = Wcat[k][n], fp16
__device__ __half g_B2h[512 * 512];           // GEMM2 B: [h][j] = W3flat[j][h], fp16
__device__ float  g_bias1[512];               // b1 + b2 (flattened c*32+s)
__device__ float  g_bias2[512];               // sum_c b3[c][:]
__device__ __half g_Hh[(size_t)65536 * 512];  // intermediate h, fp16

// ---------------------------------------------------------------------------
// Helpers (plain sm_80+ PTX only)
// ---------------------------------------------------------------------------
__device__ __forceinline__ void cp16(uint32_t smem_dst, const void* gsrc) {
    asm volatile("cp.async.cg.shared.global [%0], [%1], 16;" :: "r"(smem_dst), "l"(gsrc));
}
__device__ __forceinline__ void cp_commit() { asm volatile("cp.async.commit_group;"); }
template <int N>
__device__ __forceinline__ void cp_wait() { asm volatile("cp.async.wait_group %0;" :: "n"(N)); }

__device__ __forceinline__ uint32_t pack_h2(float lo, float hi) {
    __half2 h = __floats2half2_rn(lo, hi);
    return *reinterpret_cast<uint32_t*>(&h);
}

// m16n8k16 fp16 mma, fp32 accum.
__device__ __forceinline__ void mma16(float* d, const uint32_t* a, uint32_t b0, uint32_t b1) {
    asm volatile(
        "mma.sync.aligned.m16n8k16.row.col.f32.f16.f16.f32 "
        "{%0,%1,%2,%3}, {%4,%5,%6,%7}, {%8,%9}, {%0,%1,%2,%3};"
        : "+f"(d[0]), "+f"(d[1]), "+f"(d[2]), "+f"(d[3])
        : "r"(a[0]), "r"(a[1]), "r"(a[2]), "r"(a[3]), "r"(b0), "r"(b1));
}

// ---------------------------------------------------------------------------
// Prep: transpose weights -> fp16, fuse biases
// ---------------------------------------------------------------------------
__global__ void prep_kernel(const float* __restrict__ W1, const float* __restrict__ b1,
                            const float* __restrict__ W2, const float* __restrict__ b2,
                            const float* __restrict__ W3, const float* __restrict__ b3) {
    int idx = blockIdx.x * 256 + threadIdx.x;
    if (idx < 512 * 1536) {  // B1h[n][k] = Wcat[k][n];  n = c*32+s
        int n = idx / 1536, k = idx % 1536;
        int c = n >> 5, s = n & 31;
        float v = (k < APPD) ? W1[((size_t)c * APPD + k) * 32 + s]
                             : W2[((size_t)c * SPDIM + (k - APPD)) * 32 + s];
        g_B1h[idx] = __float2half_rn(v);
        return;
    }
    int i2 = idx - 512 * 1536;
    if (i2 < 512 * 512) {  // B2h[h][j] = W3flat[j][h]
        int h = i2 / 512, j = i2 % 512;
        g_B2h[i2] = __float2half_rn(W3[(size_t)j * 512 + h]);
        return;
    }
    int i3 = i2 - 512 * 512;
    if (i3 < 512) { g_bias1[i3] = b1[i3] + b2[i3]; return; }
    int i4 = i3 - 512;
    if (i4 < 512) {
        float s = 0.f;
        #pragma unroll
        for (int c = 0; c < 16; c++) s += b3[c * 512 + i4];
        g_bias2[i4] = s;
    }
}

// ---------------------------------------------------------------------------
// MODE1 A staging: issue LDG fp32 into regs (no dependent op -> no stall)
// ---------------------------------------------------------------------------
__device__ __forceinline__ void ldg_A(int tid, int row0, int kt, float4* st,
                                      const float* __restrict__ A0,
                                      const float* __restrict__ A1) {
    const float* abase; int lda;
    if (kt * BK < APPD) { abase = A0 + kt * BK; lda = APPD; }
    else                { abase = A1 + (kt * BK - APPD); lda = SPDIM; }
    #pragma unroll
    for (int i = 0; i < 8; i++) {
        int v = i * 128 + tid;
        int r = v >> 3, q = v & 7;
        const float* src = abase + (size_t)(row0 + r) * lda + 8 * q;
        st[2 * i]     = *(const float4*)(src);
        st[2 * i + 1] = *(const float4*)(src + 4);
    }
}
// cvt + STS of staged A (runs after the stage's MMAs -> LDG latency hidden)
__device__ __forceinline__ void sts_A(int tid, char* smemA, const float4* st) {
    #pragma unroll
    for (int i = 0; i < 8; i++) {
        int v = i * 128 + tid;
        int r = v >> 3, q = v & 7;
        uint32_t h[4] = { pack_h2(st[2*i].x,   st[2*i].y),
                          pack_h2(st[2*i].z,   st[2*i].w),
                          pack_h2(st[2*i+1].x, st[2*i+1].y),
                          pack_h2(st[2*i+1].z, st[2*i+1].w) };
        *(uint4*)(smemA + r * 128 + ((16 * q) ^ (16 * (r & 7)))) = *(const uint4*)h;
    }
}

// fp16 tile via cp.async (B both modes; A in MODE2), swizzled 128B rows
__device__ __forceinline__ void load_h16_tile(int tid, int n0g, int kt, int ldk,
                                              uint32_t s_dst, const __half* __restrict__ B) {
    #pragma unroll
    for (int i = 0; i < 8; i++) {
        int v = i * 128 + tid;
        int r = v >> 3, q = v & 7;
        cp16(s_dst + (uint32_t)(r * 128 + ((16 * q) ^ (16 * (r & 7)))),
             B + (size_t)(n0g + r) * ldk + kt * BK + 8 * q);
    }
}

// ---------------------------------------------------------------------------
// GEMM: MODE 1: [app|sp](fp32, reg-staged->fp16) @ B1h -> bias+relu -> g_Hh
//       MODE 2: g_Hh @ B2h -> bias+relu -> out (fp32)
// CTA 128x128x64, 4 warps (2x2), warp tile 64x64, fp16 HMMA fp32 accum.
// Two barriers per stage: sync1 makes stage t visible; sync2 (trailing) fences
// stage t's readers against next iteration's cp.async/STS writers (WAR).
// ---------------------------------------------------------------------------
template <int MODE>
__global__ void __launch_bounds__(128, 2)
gemm_h(const float* __restrict__ A0, const float* __restrict__ A1,
       float* __restrict__ outp) {
    extern __shared__ char smem[];
    constexpr int ABYTES = BM * BK * 2;
    constexpr int STAGE  = ABYTES + BN * BK * 2;
    constexpr int NT     = (MODE == 1) ? (1536 / BK) : (512 / BK);

    const int tid = threadIdx.x;
    const int ncol0 = blockIdx.x * BN;   // n fastest -> A-sharing CTAs co-resident
    const int row0  = blockIdx.y * BM;
    const int lane = tid & 31, wid = tid >> 5;
    const int m0 = (wid & 1) * 64;
    const int n0 = (wid >> 1) * 64;
    const int g = lane >> 2, c = lane & 3;
    const int fxor = 16 * (g & 7);

    const __half* __restrict__ Bg = (MODE == 1) ? g_B1h : g_B2h;
    const int ldb = (MODE == 1) ? 1536 : 512;

    float acc[4][8][4];
    #pragma unroll
    for (int mt = 0; mt < 4; mt++)
        #pragma unroll
        for (int nt = 0; nt < 8; nt++)
            #pragma unroll
            for (int q = 0; q < 4; q++) acc[mt][nt][q] = 0.f;

    float4 st[16];  // MODE1 A staging regs

    // ---- prologue: stage 0 ----
    {
        uint32_t s0 = (uint32_t)__cvta_generic_to_shared(smem);
        if (MODE == 1) {
            ldg_A(tid, row0, 0, st, A0, A1);
            load_h16_tile(tid, ncol0, 0, ldb, s0 + ABYTES, Bg);
            cp_commit();
            sts_A(tid, smem, st);  // one exposed LDG stall, prologue only
        } else {
            load_h16_tile(tid, row0, 0, 512, s0, g_Hh);
            load_h16_tile(tid, ncol0, 0, ldb, s0 + ABYTES, Bg);
            cp_commit();
        }
    }

    for (int t = 0; t < NT; t++) {
        char* nb = smem + ((t + 1) & 1) * STAGE;
        uint32_t nbs = (uint32_t)__cvta_generic_to_shared(nb);
        if (t + 1 < NT) {
            if (MODE == 1) {
                ldg_A(tid, row0, t + 1, st, A0, A1);  // issue only; hidden by MMAs
            } else {
                load_h16_tile(tid, row0, t + 1, 512, nbs, g_Hh);
            }
            load_h16_tile(tid, ncol0, t + 1, ldb, nbs + ABYTES, Bg);
            cp_commit();
            cp_wait<1>();
        } else {
            cp_wait<0>();
        }
        __syncthreads();  // sync1: stage t fully visible to all warps

        const char* As = smem + (t & 1) * STAGE;
        const char* Bs = As + ABYTES;

        #pragma unroll
        for (int j = 0; j < 4; j++) {  // 4 x k16
            uint32_t a[4][4];
            #pragma unroll
            for (int mt = 0; mt < 4; mt++) {
                const char* ar0 = As + (m0 + 16 * mt + g) * 128;
                const char* ar1 = ar0 + 8 * 128;
                a[mt][0] = *(const uint32_t*)(ar0 + ((4 * c + 32 * j) ^ fxor));
                a[mt][1] = *(const uint32_t*)(ar1 + ((4 * c + 32 * j) ^ fxor));
                a[mt][2] = *(const uint32_t*)(ar0 + ((4 * c + 32 * j + 16) ^ fxor));
                a[mt][3] = *(const uint32_t*)(ar1 + ((4 * c + 32 * j + 16) ^ fxor));
            }
            #pragma unroll
            for (int nt = 0; nt < 8; nt++) {
                const char* br = Bs + (n0 + 8 * nt + g) * 128;
                uint32_t b0 = *(const uint32_t*)(br + ((4 * c + 32 * j) ^ fxor));
                uint32_t b1 = *(const uint32_t*)(br + ((4 * c + 32 * j + 16) ^ fxor));
                #pragma unroll
                for (int mt = 0; mt < 4; mt++) mma16(acc[mt][nt], a[mt], b0, b1);
            }
        }

        if (MODE == 1 && t + 1 < NT) {
            sts_A(tid, nb, st);  // LDG data arrived during MMAs; store for t+1
        }
        __syncthreads();  // sync2: fence stage-t readers vs next iter's writers (WAR)
    }

    // Epilogue: bias + relu
    if (MODE == 1) {  // -> g_Hh (fp16)
        #pragma unroll
        for (int nt = 0; nt < 8; nt++) {
            const int ccol = ncol0 + n0 + 8 * nt + 2 * c;
            const float2 bv = *(const float2*)(g_bias1 + ccol);
            #pragma unroll
            for (int mt = 0; mt < 4; mt++) {
                const int r_ = row0 + m0 + 16 * mt + g;
                float x0 = fmaxf(acc[mt][nt][0] + bv.x, 0.f);
                float x1 = fmaxf(acc[mt][nt][1] + bv.y, 0.f);
                float x2 = fmaxf(acc[mt][nt][2] + bv.x, 0.f);
                float x3 = fmaxf(acc[mt][nt][3] + bv.y, 0.f);
                *(__half2*)(g_Hh + (size_t)r_ * 512 + ccol)       = __floats2half2_rn(x0, x1);
                *(__half2*)(g_Hh + (size_t)(r_ + 8) * 512 + ccol) = __floats2half2_rn(x2, x3);
            }
        }
    } else {          // -> out (fp32)
        #pragma unroll
        for (int nt = 0; nt < 8; nt++) {
            const int ccol = ncol0 + n0 + 8 * nt + 2 * c;
            const float2 bv = *(const float2*)(g_bias2 + ccol);
            #pragma unroll
            for (int mt = 0; mt < 4; mt++) {
                const int r_ = row0 + m0 + 16 * mt + g;
                float x0 = fmaxf(acc[mt][nt][0] + bv.x, 0.f);
                float x1 = fmaxf(acc[mt][nt][1] + bv.y, 0.f);
                float x2 = fmaxf(acc[mt][nt][2] + bv.x, 0.f);
                float x3 = fmaxf(acc[mt][nt][3] + bv.y, 0.f);
                *(float2*)(outp + (size_t)r_ * 512 + ccol)       = make_float2(x0, x1);
                *(float2*)(outp + (size_t)(r_ + 8) * 512 + ccol) = make_float2(x2, x3);
            }
        }
    }
}

// ---------------------------------------------------------------------------
// Launch
// ---------------------------------------------------------------------------
extern "C" void kernel_launch(void* const* d_in, const int* in_sizes, int n_in,
                              void* d_out, int out_size) {
    const float* app = (const float*)d_in[0];
    const float* sp  = (const float*)d_in[1];
    const float* W1  = (const float*)d_in[2];
    const float* b1  = (const float*)d_in[3];
    const float* W2  = (const float*)d_in[4];
    const float* b2  = (const float*)d_in[5];
    const float* W3  = (const float*)d_in[6];
    const float* b3  = (const float*)d_in[7];
    float* out = (float*)d_out;

    cudaFuncSetAttribute(gemm_h<1>, cudaFuncAttributeMaxDynamicSharedMemorySize, SMEMB);
    cudaFuncSetAttribute(gemm_h<2>, cudaFuncAttributeMaxDynamicSharedMemorySize, SMEMB);

    const int prep_elems = 512 * 1536 + 512 * 512 + 1024;
    prep_kernel<<<(prep_elems + 255) / 256, 256>>>(W1, b1, W2, b2, W3, b3);

    dim3 grid(512 / BN, NROWS / BM);  // (4, 512): n-blocks fastest -> A L2 reuse
    gemm_h<1><<<grid, 128, SMEMB>>>(app, sp, nullptr);
    gemm_h<2><<<grid, 128, SMEMB>>>(nullptr, nullptr, out);
}